// round 16
// baseline (speedup 1.0000x reference)
#include <cuda_runtime.h>
#include <cuda_bf16.h>
#include <cuda_fp16.h>
#include <cstdint>

#define N_NODES 100000
#define N_EDGES 1600000
#define D_IN    256
#define D_OUT   128

// ---------------------------------------------------------------------------
// Scratch (__device__ globals per allocation rules)
// ---------------------------------------------------------------------------
__device__ __half g_h[(size_t)N_NODES * D_OUT];   // h = x @ W^T + b (fp16)
// W fp16, pre-swizzled chunk images: 4 K-chunks x (128 rows x 128 bytes)
__device__ __align__(16) unsigned char g_Wf[4 * 16384];

// ---------------------------------------------------------------------------
// helpers
// ---------------------------------------------------------------------------
__device__ __forceinline__ uint32_t smem_u32(const void* p) {
    uint32_t a;
    asm("{ .reg .u64 t; cvta.to.shared.u64 t, %1; cvt.u32.u64 %0, t; }" : "=r"(a) : "l"(p));
    return a;
}
#define SWZ(off) ((off) ^ (((off) >> 3) & 0x70))

__device__ __forceinline__ void ldsm_x4(uint32_t* r, uint32_t addr) {
    asm volatile("ldmatrix.sync.aligned.m8n8.x4.shared.b16 {%0,%1,%2,%3}, [%4];"
                 : "=r"(r[0]), "=r"(r[1]), "=r"(r[2]), "=r"(r[3]) : "r"(addr));
}

__device__ __forceinline__ void mma_f16(float* c, const uint32_t* a,
                                        uint32_t b0, uint32_t b1) {
    asm volatile(
        "mma.sync.aligned.m16n8k16.row.col.f32.f16.f16.f32 "
        "{%0,%1,%2,%3}, {%4,%5,%6,%7}, {%8,%9}, {%0,%1,%2,%3};"
        : "+f"(c[0]), "+f"(c[1]), "+f"(c[2]), "+f"(c[3])
        : "r"(a[0]), "r"(a[1]), "r"(a[2]), "r"(a[3]), "r"(b0), "r"(b1));
}

__device__ __forceinline__ void cp16(uint32_t d, const void* s) {
    asm volatile("cp.async.cg.shared.global [%0], [%1], 16;" :: "r"(d), "l"(s));
}
#define CP_COMMIT() asm volatile("cp.async.commit_group;" ::: "memory")
#define CP_WAIT0()  asm volatile("cp.async.wait_group 0;" ::: "memory")
#define CP_WAIT1()  asm volatile("cp.async.wait_group 1;" ::: "memory")

__device__ __forceinline__ uint32_t h2u(__half2 v) { return *(uint32_t*)&v; }

// ---------------------------------------------------------------------------
// Kernel 1: convert W to fp16, pre-swizzled chunk images (once, tiny)
// ---------------------------------------------------------------------------
__global__ void prep_W(const float* __restrict__ W)
{
    int idx = blockIdx.x * blockDim.x + threadIdx.x;
    if (idx >= 128 * 256) return;
    int n = idx >> 8;          // output row (N)
    int k = idx & 255;         // K
    __half hv = __float2half_rn(W[idx]);
    int c = k >> 6, kk = k & 63;
    uint32_t off = (uint32_t)(n * 128 + kk * 2);
    uint32_t sw = SWZ(off);
    *(unsigned short*)(g_Wf + c * 16384 + sw) = *(unsigned short*)&hv;
}

// ---------------------------------------------------------------------------
// Kernel 2: fp16 mma.sync GEMM  h = x @ W^T + b  (single-term, fp32 acc)
// Proven R15 pipeline: cp.async A32 (fp32, XOR-swizzled) -> smem convert to
// A16 -> compute; B single-buffered cp.async prefetched after compute.
// 64KB smem, 2 CTAs/SM, no register live-range extensions.
// ---------------------------------------------------------------------------
#define SM_A32 0
#define SM_A16 32768
#define SM_B   49152
#define GEMM_SMEM 65536

__device__ __forceinline__ uint32_t tile_addr(uint32_t base, int row0, int k16, int lane) {
    uint32_t off = (uint32_t)((row0 + (lane & 15)) * 128 + k16 * 32 + (lane >> 4) * 16);
    return base + SWZ(off);
}

__global__ __launch_bounds__(256, 2)
void gemm_mma(const float* __restrict__ x,
              const float* __restrict__ bias,
              __half* __restrict__ hout)
{
    extern __shared__ char smem[];
    const uint32_t sb = smem_u32(smem);
    const int tid  = threadIdx.x;
    const int lane = tid & 31;
    const int wid  = tid >> 5;
    const int warpM = wid & 3;
    const int warpN = wid >> 2;

    const int m0 = blockIdx.x * 128;
    const int r  = tid >> 1;          // row this thread converts
    const int h2 = tid & 1;           // which 32-float half of the row-chunk

    auto stage_A32 = [&](int c) {
        #pragma unroll
        for (int j = 0; j < 8; j++) {
            int gi   = tid + j * 256;       // 0..2047 16B pieces
            int row  = gi >> 4;             // 0..127
            int grp  = gi & 15;             // 16B group within 256B
            int gnode = min(m0 + row, N_NODES - 1);
            const char* src = (const char*)x + (size_t)gnode * (D_IN * 4)
                              + c * 256 + grp * 16;
            uint32_t dst = sb + SM_A32 + row * 256 + (((uint32_t)(grp ^ (row & 15))) << 4);
            cp16(dst, src);
        }
    };
    auto stage_B = [&](int c) {
        const unsigned char* gbf = g_Wf + c * 16384;
        #pragma unroll
        for (int j = 0; j < 4; j++) {
            uint32_t boff = (uint32_t)(tid + j * 256) * 16;
            cp16(sb + SM_B + boff, gbf + boff);
        }
    };

    stage_A32(0);
    stage_B(0);
    CP_COMMIT();
    CP_WAIT0();
    __syncthreads();

    float acc[2][8][4];
    #pragma unroll
    for (int i = 0; i < 2; i++)
        #pragma unroll
        for (int j = 0; j < 8; j++)
            #pragma unroll
            for (int t = 0; t < 4; t++) acc[i][j][t] = 0.f;

    #pragma unroll 1
    for (int c = 0; c < 4; c++) {
        if (c > 0) {            // complete A32(c) (leaves B(c) group pending)
            CP_WAIT1();
            __syncthreads();
        }

        // --- convert A32(c) fp32 -> A16 fp16 (smem -> regs -> smem) ---
        #pragma unroll
        for (int i = 0; i < 4; i++) {
            int g0 = h2 * 8 + 2 * i;
            uint32_t base = (uint32_t)(r * 256);
            const float4 f0 = *(const float4*)(smem + SM_A32 + base
                                + (((uint32_t)(g0       ^ (r & 15))) << 4));
            const float4 f1 = *(const float4*)(smem + SM_A32 + base
                                + (((uint32_t)((g0 + 1) ^ (r & 15))) << 4));
            __half2 H0 = __floats2half2_rn(f0.x, f0.y);
            __half2 H1 = __floats2half2_rn(f0.z, f0.w);
            __half2 H2 = __floats2half2_rn(f1.x, f1.y);
            __half2 H3 = __floats2half2_rn(f1.z, f1.w);
            uint32_t off = (uint32_t)(r * 128 + h2 * 64 + i * 16);
            *(uint4*)(smem + SM_A16 + SWZ(off)) =
                make_uint4(h2u(H0), h2u(H1), h2u(H2), h2u(H3));
        }
        __syncthreads();                 // A16 ready; A32 buffer free

        if (c < 3) { stage_A32(c + 1); CP_COMMIT(); }

        if (c < 3) CP_WAIT1(); else CP_WAIT0();
        __syncthreads();

        // --- compute chunk c: 4 k16 steps ---
        #pragma unroll
        for (int k16 = 0; k16 < 4; k16++) {
            uint32_t Ah[2][4];
            #pragma unroll
            for (int mf = 0; mf < 2; mf++)
                ldsm_x4(Ah[mf], tile_addr(sb + SM_A16, warpM * 32 + mf * 16, k16, lane));
            #pragma unroll
            for (int j = 0; j < 4; j++) {
                uint32_t B[4];
                ldsm_x4(B, tile_addr(sb + SM_B, warpN * 64 + j * 16, k16, lane));
                #pragma unroll
                for (int mf = 0; mf < 2; mf++) {
                    mma_f16(acc[mf][2 * j],     Ah[mf], B[0], B[2]);
                    mma_f16(acc[mf][2 * j + 1], Ah[mf], B[1], B[3]);
                }
            }
        }
        __syncthreads();                 // compute done; B buffer free

        if (c < 3) { stage_B(c + 1); CP_COMMIT(); }
    }

    // --- epilogue: registers -> fp16 gmem with bias ---
    const int g  = lane >> 2;
    const int tg = lane & 3;
    #pragma unroll
    for (int mf = 0; mf < 2; mf++) {
        #pragma unroll
        for (int nf = 0; nf < 8; nf++) {
            int col = warpN * 64 + nf * 8 + tg * 2;
            float b0 = bias[col], b1 = bias[col + 1];
            int row = m0 + warpM * 32 + mf * 16 + g;
            if (row < N_NODES) {
                __half2 v = __floats2half2_rn(acc[mf][nf][0] + b0, acc[mf][nf][1] + b1);
                *(__half2*)&hout[(size_t)row * D_OUT + col] = v;
            }
            if (row + 8 < N_NODES) {
                __half2 v = __floats2half2_rn(acc[mf][nf][2] + b0, acc[mf][nf][3] + b1);
                *(__half2*)&hout[(size_t)(row + 8) * D_OUT + col] = v;
            }
        }
    }
}

// ---------------------------------------------------------------------------
// Kernel 3: zero the output — grid-stride fill
// ---------------------------------------------------------------------------
__global__ void zero_out(float4* __restrict__ out, int n4)
{
    const int stride = gridDim.x * blockDim.x;
    for (int i = blockIdx.x * blockDim.x + threadIdx.x; i < n4; i += stride)
        out[i] = make_float4(0.f, 0.f, 0.f, 0.f);
}

// ---------------------------------------------------------------------------
// Kernel 4: edge gather + segment-sum scatter (dst sorted).
// 2048 edges/block, 256 threads = 8 warps x 256 edges (same per-warp loop as
// the proven 128-thread version; fewer blocks amortize staging/dtype-check
// and raise resident-warp count). Lane owns 4 channels (uint2 of fp16).
// Unroll-4. Owned segments -> STG.128; boundary segments -> atomics.
// ---------------------------------------------------------------------------
#define EPB 2048
#define EPW 256

__global__ __launch_bounds__(256)
void edge_scatter(const void* __restrict__ srcRaw,
                  const void* __restrict__ dstRaw,
                  const float* __restrict__ w,
                  const __half* __restrict__ h,
                  float* __restrict__ out)
{
    __shared__ int4 s_meta[EPB];     // (src, dst, w_bits, pad)
    __shared__ int  s_flags;

    const int tid = threadIdx.x;
    const int e0  = blockIdx.x * EPB;
    const int cnt = min(EPB, N_EDGES - e0);

    if (tid == 0) {
        const int* a32 = (const int*)srcRaw;
        const int* b32 = (const int*)dstRaw;
        int fs = 1, fd = 1;
        #pragma unroll
        for (int i = 0; i < 8; i++) {
            int k = (i + 1) * (N_EDGES / 20);
            if (a32[2 * k + 1] != 0) fs = 0;
            if (b32[2 * k + 1] != 0) fd = 0;
        }
        s_flags = fs | (fd << 1);
    }
    __syncthreads();
    const int is64s = s_flags & 1;
    const int is64d = (s_flags >> 1) & 1;

    const long long* sll = (const long long*)srcRaw;
    const long long* dll = (const long long*)dstRaw;
    const int*       s32 = (const int*)srcRaw;
    const int*       d32 = (const int*)dstRaw;

    for (int i = tid; i < cnt; i += 256) {
        int sv = is64s ? (int)sll[e0 + i] : s32[e0 + i];
        int dv = is64d ? (int)dll[e0 + i] : d32[e0 + i];
        sv = min(max(sv, 0), N_NODES - 1);
        dv = min(max(dv, 0), N_NODES - 1);
        s_meta[i] = make_int4(sv, dv, __float_as_int(w[e0 + i]), 0);
    }
    __syncthreads();

    const int g    = tid >> 5;
    const int lane = tid & 31;
    const int j0   = g * EPW;
    if (j0 >= cnt) return;
    const int jend = min(j0 + EPW, cnt);

    const uint2* hl = (const uint2*)h + lane;   // 32 uint2 per row

    float4 acc = make_float4(0.f, 0.f, 0.f, 0.f);
    int cur = s_meta[j0].y;
    int seg_start = j0;

    for (int j = j0; j < jend; j += 4) {
        int4 m[4];
        uint2 hv[4];
        #pragma unroll
        for (int t = 0; t < 4; t++) m[t] = s_meta[j + t];
        #pragma unroll
        for (int t = 0; t < 4; t++) hv[t] = __ldg(hl + (size_t)m[t].x * 32);

        #pragma unroll
        for (int t = 0; t < 4; t++) {
            if (m[t].y != cur) {
                float* p = &out[(size_t)cur * D_OUT + lane * 4];
                if (seg_start > j0) {
                    *(float4*)p = acc;             // exclusively owned segment
                } else {
                    atomicAdd(p + 0, acc.x); atomicAdd(p + 1, acc.y);
                    atomicAdd(p + 2, acc.z); atomicAdd(p + 3, acc.w);
                }
                acc = make_float4(0.f, 0.f, 0.f, 0.f);
                cur = m[t].y;
                seg_start = j + t;
            }
            float2 lo = __half22float2(*(__half2*)&hv[t].x);
            float2 hi = __half22float2(*(__half2*)&hv[t].y);
            float wv = __int_as_float(m[t].z);
            acc.x = fmaf(wv, lo.x, acc.x);
            acc.y = fmaf(wv, lo.y, acc.y);
            acc.z = fmaf(wv, hi.x, acc.z);
            acc.w = fmaf(wv, hi.y, acc.w);
        }
    }
    float* p = &out[(size_t)cur * D_OUT + lane * 4];
    atomicAdd(p + 0, acc.x); atomicAdd(p + 1, acc.y);
    atomicAdd(p + 2, acc.z); atomicAdd(p + 3, acc.w);
}

// ---------------------------------------------------------------------------
// launch
// ---------------------------------------------------------------------------
extern "C" void kernel_launch(void* const* d_in, const int* in_sizes, int n_in,
                              void* d_out, int out_size)
{
    const float* x    = (const float*)d_in[0];
    const void*  srcR = d_in[1];
    const void*  dstR = d_in[2];
    const float* w    = (const float*)d_in[3];
    const float* W    = (const float*)d_in[4];
    const float* b    = (const float*)d_in[5];
    float*       out  = (float*)d_out;

    __half* h = nullptr;
    cudaGetSymbolAddress((void**)&h, g_h);

    cudaFuncSetAttribute(gemm_mma, cudaFuncAttributeMaxDynamicSharedMemorySize, GEMM_SMEM);

    prep_W<<<128, 256>>>(W);
    gemm_mma<<<(N_NODES + 127) / 128, 256, GEMM_SMEM>>>(x, b, h);

    int n4 = (N_NODES * D_OUT) / 4;
    zero_out<<<296, 256>>>((float4*)out, n4);

    edge_scatter<<<(N_EDGES + EPB - 1) / EPB, 256>>>(srcR, dstR, w, h, out);
}

// round 17
// speedup vs baseline: 1.0386x; 1.0386x over previous
#include <cuda_runtime.h>
#include <cuda_bf16.h>
#include <cuda_fp16.h>
#include <cstdint>

#define N_NODES 100000
#define N_EDGES 1600000
#define D_IN    256
#define D_OUT   128

// ---------------------------------------------------------------------------
// Scratch (__device__ globals per allocation rules)
// ---------------------------------------------------------------------------
__device__ __half g_h[(size_t)N_NODES * D_OUT];   // h = x @ W^T + b (fp16)
// W fp16, pre-swizzled chunk images: 4 K-chunks x (128 rows x 128 bytes)
__device__ __align__(16) unsigned char g_Wf[4 * 16384];

// ---------------------------------------------------------------------------
// helpers
// ---------------------------------------------------------------------------
__device__ __forceinline__ uint32_t smem_u32(const void* p) {
    uint32_t a;
    asm("{ .reg .u64 t; cvta.to.shared.u64 t, %1; cvt.u32.u64 %0, t; }" : "=r"(a) : "l"(p));
    return a;
}
#define SWZ(off) ((off) ^ (((off) >> 3) & 0x70))

__device__ __forceinline__ void ldsm_x4(uint32_t* r, uint32_t addr) {
    asm volatile("ldmatrix.sync.aligned.m8n8.x4.shared.b16 {%0,%1,%2,%3}, [%4];"
                 : "=r"(r[0]), "=r"(r[1]), "=r"(r[2]), "=r"(r[3]) : "r"(addr));
}

__device__ __forceinline__ void mma_f16(float* c, const uint32_t* a,
                                        uint32_t b0, uint32_t b1) {
    asm volatile(
        "mma.sync.aligned.m16n8k16.row.col.f32.f16.f16.f32 "
        "{%0,%1,%2,%3}, {%4,%5,%6,%7}, {%8,%9}, {%0,%1,%2,%3};"
        : "+f"(c[0]), "+f"(c[1]), "+f"(c[2]), "+f"(c[3])
        : "r"(a[0]), "r"(a[1]), "r"(a[2]), "r"(a[3]), "r"(b0), "r"(b1));
}

__device__ __forceinline__ void cp16(uint32_t d, const void* s) {
    asm volatile("cp.async.cg.shared.global [%0], [%1], 16;" :: "r"(d), "l"(s));
}
#define CP_COMMIT() asm volatile("cp.async.commit_group;" ::: "memory")
#define CP_WAIT0()  asm volatile("cp.async.wait_group 0;" ::: "memory")
#define CP_WAIT1()  asm volatile("cp.async.wait_group 1;" ::: "memory")

__device__ __forceinline__ uint32_t h2u(__half2 v) { return *(uint32_t*)&v; }

// ---------------------------------------------------------------------------
// Kernel 1: fused prep — blocks 0..127 convert W to pre-swizzled fp16 images;
// blocks 128+ grid-stride zero the output buffer. Independent tasks fused to
// save one launch + gap.
// ---------------------------------------------------------------------------
#define ZERO_BLOCKS 296
__global__ void prep_and_zero(const float* __restrict__ W,
                              float4* __restrict__ out, int n4)
{
    if (blockIdx.x < 128) {
        int idx = blockIdx.x * 256 + threadIdx.x;
        int n = idx >> 8;          // output row (N)
        int k = idx & 255;         // K
        __half hv = __float2half_rn(W[idx]);
        int c = k >> 6, kk = k & 63;
        uint32_t off = (uint32_t)(n * 128 + kk * 2);
        uint32_t sw = SWZ(off);
        *(unsigned short*)(g_Wf + c * 16384 + sw) = *(unsigned short*)&hv;
    } else {
        const int stride = ZERO_BLOCKS * 256;
        for (int i = (blockIdx.x - 128) * 256 + threadIdx.x; i < n4; i += stride)
            out[i] = make_float4(0.f, 0.f, 0.f, 0.f);
    }
}

// ---------------------------------------------------------------------------
// Kernel 2: fp16 mma.sync GEMM  h = x @ W^T + b  (single-term, fp32 acc)
// Proven R15 pipeline: cp.async A32 (fp32, XOR-swizzled) -> smem convert to
// A16 -> compute; B single-buffered cp.async prefetched after compute.
// 64KB smem, 2 CTAs/SM, no register live-range extensions.
// ---------------------------------------------------------------------------
#define SM_A32 0
#define SM_A16 32768
#define SM_B   49152
#define GEMM_SMEM 65536

__device__ __forceinline__ uint32_t tile_addr(uint32_t base, int row0, int k16, int lane) {
    uint32_t off = (uint32_t)((row0 + (lane & 15)) * 128 + k16 * 32 + (lane >> 4) * 16);
    return base + SWZ(off);
}

__global__ __launch_bounds__(256, 2)
void gemm_mma(const float* __restrict__ x,
              const float* __restrict__ bias,
              __half* __restrict__ hout)
{
    extern __shared__ char smem[];
    const uint32_t sb = smem_u32(smem);
    const int tid  = threadIdx.x;
    const int lane = tid & 31;
    const int wid  = tid >> 5;
    const int warpM = wid & 3;
    const int warpN = wid >> 2;

    const int m0 = blockIdx.x * 128;
    const int r  = tid >> 1;          // row this thread converts
    const int h2 = tid & 1;           // which 32-float half of the row-chunk

    auto stage_A32 = [&](int c) {
        #pragma unroll
        for (int j = 0; j < 8; j++) {
            int gi   = tid + j * 256;       // 0..2047 16B pieces
            int row  = gi >> 4;             // 0..127
            int grp  = gi & 15;             // 16B group within 256B
            int gnode = min(m0 + row, N_NODES - 1);
            const char* src = (const char*)x + (size_t)gnode * (D_IN * 4)
                              + c * 256 + grp * 16;
            uint32_t dst = sb + SM_A32 + row * 256 + (((uint32_t)(grp ^ (row & 15))) << 4);
            cp16(dst, src);
        }
    };
    auto stage_B = [&](int c) {
        const unsigned char* gbf = g_Wf + c * 16384;
        #pragma unroll
        for (int j = 0; j < 4; j++) {
            uint32_t boff = (uint32_t)(tid + j * 256) * 16;
            cp16(sb + SM_B + boff, gbf + boff);
        }
    };

    stage_A32(0);
    stage_B(0);
    CP_COMMIT();
    CP_WAIT0();
    __syncthreads();

    float acc[2][8][4];
    #pragma unroll
    for (int i = 0; i < 2; i++)
        #pragma unroll
        for (int j = 0; j < 8; j++)
            #pragma unroll
            for (int t = 0; t < 4; t++) acc[i][j][t] = 0.f;

    #pragma unroll 1
    for (int c = 0; c < 4; c++) {
        if (c > 0) {            // complete A32(c) (leaves B(c) group pending)
            CP_WAIT1();
            __syncthreads();
        }

        // --- convert A32(c) fp32 -> A16 fp16 (smem -> regs -> smem) ---
        #pragma unroll
        for (int i = 0; i < 4; i++) {
            int g0 = h2 * 8 + 2 * i;
            uint32_t base = (uint32_t)(r * 256);
            const float4 f0 = *(const float4*)(smem + SM_A32 + base
                                + (((uint32_t)(g0       ^ (r & 15))) << 4));
            const float4 f1 = *(const float4*)(smem + SM_A32 + base
                                + (((uint32_t)((g0 + 1) ^ (r & 15))) << 4));
            __half2 H0 = __floats2half2_rn(f0.x, f0.y);
            __half2 H1 = __floats2half2_rn(f0.z, f0.w);
            __half2 H2 = __floats2half2_rn(f1.x, f1.y);
            __half2 H3 = __floats2half2_rn(f1.z, f1.w);
            uint32_t off = (uint32_t)(r * 128 + h2 * 64 + i * 16);
            *(uint4*)(smem + SM_A16 + SWZ(off)) =
                make_uint4(h2u(H0), h2u(H1), h2u(H2), h2u(H3));
        }
        __syncthreads();                 // A16 ready; A32 buffer free

        if (c < 3) { stage_A32(c + 1); CP_COMMIT(); }

        if (c < 3) CP_WAIT1(); else CP_WAIT0();
        __syncthreads();

        // --- compute chunk c: 4 k16 steps ---
        #pragma unroll
        for (int k16 = 0; k16 < 4; k16++) {
            uint32_t Ah[2][4];
            #pragma unroll
            for (int mf = 0; mf < 2; mf++)
                ldsm_x4(Ah[mf], tile_addr(sb + SM_A16, warpM * 32 + mf * 16, k16, lane));
            #pragma unroll
            for (int j = 0; j < 4; j++) {
                uint32_t B[4];
                ldsm_x4(B, tile_addr(sb + SM_B, warpN * 64 + j * 16, k16, lane));
                #pragma unroll
                for (int mf = 0; mf < 2; mf++) {
                    mma_f16(acc[mf][2 * j],     Ah[mf], B[0], B[2]);
                    mma_f16(acc[mf][2 * j + 1], Ah[mf], B[1], B[3]);
                }
            }
        }
        __syncthreads();                 // compute done; B buffer free

        if (c < 3) { stage_B(c + 1); CP_COMMIT(); }
    }

    // --- epilogue: registers -> fp16 gmem with bias ---
    const int g  = lane >> 2;
    const int tg = lane & 3;
    #pragma unroll
    for (int mf = 0; mf < 2; mf++) {
        #pragma unroll
        for (int nf = 0; nf < 8; nf++) {
            int col = warpN * 64 + nf * 8 + tg * 2;
            float b0 = bias[col], b1 = bias[col + 1];
            int row = m0 + warpM * 32 + mf * 16 + g;
            if (row < N_NODES) {
                __half2 v = __floats2half2_rn(acc[mf][nf][0] + b0, acc[mf][nf][1] + b1);
                *(__half2*)&hout[(size_t)row * D_OUT + col] = v;
            }
            if (row + 8 < N_NODES) {
                __half2 v = __floats2half2_rn(acc[mf][nf][2] + b0, acc[mf][nf][3] + b1);
                *(__half2*)&hout[(size_t)(row + 8) * D_OUT + col] = v;
            }
        }
    }
}

// ---------------------------------------------------------------------------
// Kernel 3: edge gather + segment-sum scatter (dst sorted). Proven R15 config:
// 1024 edges/block, 4 warps x 256 edges; lane owns 4 channels (uint2 of fp16).
// Unroll-4. Owned segments -> STG.128; boundary segments -> atomics.
// ---------------------------------------------------------------------------
#define EPB 1024
#define EPW 256

__global__ __launch_bounds__(128)
void edge_scatter(const void* __restrict__ srcRaw,
                  const void* __restrict__ dstRaw,
                  const float* __restrict__ w,
                  const __half* __restrict__ h,
                  float* __restrict__ out)
{
    __shared__ int4 s_meta[EPB];     // (src, dst, w_bits, pad)
    __shared__ int  s_flags;

    const int tid = threadIdx.x;
    const int e0  = blockIdx.x * EPB;
    const int cnt = min(EPB, N_EDGES - e0);

    if (tid == 0) {
        const int* a32 = (const int*)srcRaw;
        const int* b32 = (const int*)dstRaw;
        int fs = 1, fd = 1;
        #pragma unroll
        for (int i = 0; i < 8; i++) {
            int k = (i + 1) * (N_EDGES / 20);
            if (a32[2 * k + 1] != 0) fs = 0;
            if (b32[2 * k + 1] != 0) fd = 0;
        }
        s_flags = fs | (fd << 1);
    }
    __syncthreads();
    const int is64s = s_flags & 1;
    const int is64d = (s_flags >> 1) & 1;

    const long long* sll = (const long long*)srcRaw;
    const long long* dll = (const long long*)dstRaw;
    const int*       s32 = (const int*)srcRaw;
    const int*       d32 = (const int*)dstRaw;

    for (int i = tid; i < cnt; i += 128) {
        int sv = is64s ? (int)sll[e0 + i] : s32[e0 + i];
        int dv = is64d ? (int)dll[e0 + i] : d32[e0 + i];
        sv = min(max(sv, 0), N_NODES - 1);
        dv = min(max(dv, 0), N_NODES - 1);
        s_meta[i] = make_int4(sv, dv, __float_as_int(w[e0 + i]), 0);
    }
    __syncthreads();

    const int g    = tid >> 5;
    const int lane = tid & 31;
    const int j0   = g * EPW;
    if (j0 >= cnt) return;
    const int jend = min(j0 + EPW, cnt);

    const uint2* hl = (const uint2*)h + lane;   // 32 uint2 per row

    float4 acc = make_float4(0.f, 0.f, 0.f, 0.f);
    int cur = s_meta[j0].y;
    int seg_start = j0;

    for (int j = j0; j < jend; j += 4) {
        int4 m[4];
        uint2 hv[4];
        #pragma unroll
        for (int t = 0; t < 4; t++) m[t] = s_meta[j + t];
        #pragma unroll
        for (int t = 0; t < 4; t++) hv[t] = __ldg(hl + (size_t)m[t].x * 32);

        #pragma unroll
        for (int t = 0; t < 4; t++) {
            if (m[t].y != cur) {
                float* p = &out[(size_t)cur * D_OUT + lane * 4];
                if (seg_start > j0) {
                    *(float4*)p = acc;             // exclusively owned segment
                } else {
                    atomicAdd(p + 0, acc.x); atomicAdd(p + 1, acc.y);
                    atomicAdd(p + 2, acc.z); atomicAdd(p + 3, acc.w);
                }
                acc = make_float4(0.f, 0.f, 0.f, 0.f);
                cur = m[t].y;
                seg_start = j + t;
            }
            float2 lo = __half22float2(*(__half2*)&hv[t].x);
            float2 hi = __half22float2(*(__half2*)&hv[t].y);
            float wv = __int_as_float(m[t].z);
            acc.x = fmaf(wv, lo.x, acc.x);
            acc.y = fmaf(wv, lo.y, acc.y);
            acc.z = fmaf(wv, hi.x, acc.z);
            acc.w = fmaf(wv, hi.y, acc.w);
        }
    }
    float* p = &out[(size_t)cur * D_OUT + lane * 4];
    atomicAdd(p + 0, acc.x); atomicAdd(p + 1, acc.y);
    atomicAdd(p + 2, acc.z); atomicAdd(p + 3, acc.w);
}

// ---------------------------------------------------------------------------
// launch
// ---------------------------------------------------------------------------
extern "C" void kernel_launch(void* const* d_in, const int* in_sizes, int n_in,
                              void* d_out, int out_size)
{
    const float* x    = (const float*)d_in[0];
    const void*  srcR = d_in[1];
    const void*  dstR = d_in[2];
    const float* w    = (const float*)d_in[3];
    const float* W    = (const float*)d_in[4];
    const float* b    = (const float*)d_in[5];
    float*       out  = (float*)d_out;

    __half* h = nullptr;
    cudaGetSymbolAddress((void**)&h, g_h);

    cudaFuncSetAttribute(gemm_mma, cudaFuncAttributeMaxDynamicSharedMemorySize, GEMM_SMEM);

    int n4 = (N_NODES * D_OUT) / 4;
    prep_and_zero<<<128 + ZERO_BLOCKS, 256>>>(W, (float4*)out, n4);
    gemm_mma<<<(N_NODES + 127) / 128, 256, GEMM_SMEM>>>(x, b, h);
    edge_scatter<<<(N_EDGES + EPB - 1) / EPB, 128>>>(srcR, dstR, w, h, out);
}